// round 8
// baseline (speedup 1.0000x reference)
#include <cuda_runtime.h>
#include <cuda_bf16.h>
#include <math.h>
#include <stdint.h>

#define N_TOK 16384
#define D 512
#define SEQL 1024
#define BSZ 16
#define DFF 2048
#define ATT_SCALE 0.125f

typedef __nv_bfloat16 bf16;

// -------------------- fp32 scratch --------------------
__device__ float d_M1[D * D];
__device__ float d_M3[D * D];
__device__ float d_B0[(size_t)N_TOK * D];
__device__ float d_B1[(size_t)N_TOK * D];
__device__ float d_B2[(size_t)N_TOK * D];
__device__ float d_B3[(size_t)N_TOK * D];
__device__ float d_B4[(size_t)N_TOK * D];

// -------------------- split-bf16 weights --------------------
#define OFF_WKG 0
#define OFF_WQG 262144
#define OFF_M1  524288
#define OFF_FCG 786432
#define OFF_M3  1048576
#define OFF_W1  1310720
#define OFF_W2  2359296
#define W_TOTAL 3407872
__device__ bf16 d_Wh[W_TOTAL];
__device__ bf16 d_Wl[W_TOTAL];

// -------------------- split-bf16 activations --------------------
#define ACT_N ((size_t)N_TOK * D)
__device__ bf16 d_XH[ACT_N],   d_XL[ACT_N];     // input split
__device__ bf16 d_C1H[ACT_N],  d_C1L[ACT_N];    // conv1 out
__device__ bf16 d_QH[ACT_N],   d_QL[ACT_N];     // Q
__device__ bf16 d_KH[ACT_N],   d_KL[ACT_N];     // Kg
__device__ bf16 d_VB[ACT_N];                     // Vg plain bf16
__device__ bf16 d_ATH[ACT_N],  d_ATL[ACT_N];    // attention out
__device__ bf16 d_X2CH[ACT_N], d_X2CL[ACT_N];   // x2c
__device__ bf16 d_X2H[ACT_N],  d_X2L[ACT_N];    // x2
__device__ bf16 d_X3H[ACT_N],  d_X3L[ACT_N];    // x3
__device__ bf16 d_HIDH[(size_t)N_TOK * DFF], d_HIDL[(size_t)N_TOK * DFF];

// ==================== helpers ====================
__device__ __forceinline__ uint32_t smem_u32(const void* p) {
    uint32_t a;
    asm("{ .reg .u64 t; cvta.to.shared.u64 t, %1; cvt.u32.u64 %0, t; }" : "=r"(a) : "l"(p));
    return a;
}
__device__ __forceinline__ void ldsm4(uint32_t addr, uint32_t& r0, uint32_t& r1, uint32_t& r2, uint32_t& r3) {
    asm volatile("ldmatrix.sync.aligned.m8n8.x4.shared.b16 {%0,%1,%2,%3}, [%4];"
                 : "=r"(r0), "=r"(r1), "=r"(r2), "=r"(r3) : "r"(addr));
}
__device__ __forceinline__ void mma_bf16(float c[4], const uint32_t a[4], uint32_t b0, uint32_t b1) {
    asm volatile(
        "mma.sync.aligned.m16n8k16.row.col.f32.bf16.bf16.f32 "
        "{%0,%1,%2,%3}, {%4,%5,%6,%7}, {%8,%9}, {%0,%1,%2,%3};"
        : "+f"(c[0]), "+f"(c[1]), "+f"(c[2]), "+f"(c[3])
        : "r"(a[0]), "r"(a[1]), "r"(a[2]), "r"(a[3]), "r"(b0), "r"(b1));
}
// split pair of fp32 into packed bf16x2 hi/lo
__device__ __forceinline__ void splitf2(float x, float y, uint32_t& h, uint32_t& l) {
    __nv_bfloat162 hh = __float22bfloat162_rn(make_float2(x, y));
    float2 hf = __bfloat1622float2(hh);
    __nv_bfloat162 ll = __float22bfloat162_rn(make_float2(x - hf.x, y - hf.y));
    h = *(uint32_t*)&hh; l = *(uint32_t*)&ll;
}
__device__ __forceinline__ void split2(float4 v, uint2& hi, uint2& lo) {
    uint32_t h0, l0, h1, l1;
    splitf2(v.x, v.y, h0, l0);
    splitf2(v.z, v.w, h1, l1);
    hi = make_uint2(h0, h1);
    lo = make_uint2(l0, l1);
}
#define CP_ASYNC16(dst, src) asm volatile("cp.async.cg.shared.global [%0], [%1], 16;" :: "r"(dst), "l"(src) : "memory")
#define CP_COMMIT()          asm volatile("cp.async.commit_group;" ::: "memory")
#define CP_WAIT0()           asm volatile("cp.async.wait_group 0;" ::: "memory")
#define CP_WAIT1()           asm volatile("cp.async.wait_group 1;" ::: "memory")

// -------------------- generic fp32 -> bf16 hi/lo split --------------------
__global__ __launch_bounds__(256) void split_w(
    bf16* __restrict__ H, bf16* __restrict__ L, const float* __restrict__ W, int n)
{
    int i = (blockIdx.x * 256 + threadIdx.x) * 4;
    if (i < n) {
        float4 v = *(const float4*)(W + i);
        uint2 h, l; split2(v, h, l);
        *(uint2*)(H + i) = h;
        *(uint2*)(L + i) = l;
    }
}

// ==================== fully-streamed split-bf16 mma GEMM ====================
// C outputs: fp32 C (optional) and/or split bf16 Ch/Cl (optional).
// A, B both pre-split bf16 hi/lo [rows x K] row-major. 128x128 tile, BK=64.
#define T_AH 0
#define T_AL 18432
#define T_BH 36864
#define T_BL 55296
#define STG  73728
#define TCG_SMEM (2 * STG)

__global__ __launch_bounds__(256, 1) void mma_gemm(
    float* __restrict__ C, bf16* __restrict__ Ch, bf16* __restrict__ Cl,
    const bf16* __restrict__ Ah, const bf16* __restrict__ Al,
    const bf16* __restrict__ Bh, const bf16* __restrict__ Bl,
    int M, int Nt, int K, const float* __restrict__ bias, int act)
{
    extern __shared__ char smem[];
    const uint32_t sb = smem_u32(smem);
    const int tid = threadIdx.x, wid = tid >> 5, lane = tid & 31;
    const int m0 = blockIdx.y * 128, n0 = blockIdx.x * 128;
    const int wm = (wid & 3) << 5;
    const int wn = (wid >> 2) << 6;
    const int quad = lane >> 3, r = lane & 7;
    const int arow = ((quad & 1) << 3) + r, ak = (quad >> 1) << 3;
    const int brow = ((quad >> 1) << 3) + r, bk = (quad & 1) << 3;

    float acc[2][8][4];
    #pragma unroll
    for (int i = 0; i < 2; i++)
        #pragma unroll
        for (int j = 0; j < 8; j++)
            #pragma unroll
            for (int q = 0; q < 4; q++) acc[i][j][q] = 0.f;

    const int nit = K >> 6;

    // prologue: stage 0
    {
        const uint32_t bs = sb;
        #pragma unroll
        for (int j = 0; j < 4; j++) {
            int ch = tid + (j << 8);
            int row = ch >> 3, cc = ch & 7;
            uint32_t so = row * 144 + cc * 16;
            size_t ga = (size_t)(m0 + row) * K + cc * 8;
            size_t gb = (size_t)(n0 + row) * K + cc * 8;
            CP_ASYNC16(bs + T_AH + so, Ah + ga);
            CP_ASYNC16(bs + T_AL + so, Al + ga);
            CP_ASYNC16(bs + T_BH + so, Bh + gb);
            CP_ASYNC16(bs + T_BL + so, Bl + gb);
        }
        CP_COMMIT();
    }

    for (int it = 0; it < nit; it++) {
        const uint32_t cs = sb + (it & 1) * STG;
        if (it + 1 < nit) {
            const uint32_t ns = sb + ((it + 1) & 1) * STG;
            const int k0 = (it + 1) << 6;
            #pragma unroll
            for (int j = 0; j < 4; j++) {
                int ch = tid + (j << 8);
                int row = ch >> 3, cc = ch & 7;
                uint32_t so = row * 144 + cc * 16;
                size_t ga = (size_t)(m0 + row) * K + k0 + cc * 8;
                size_t gb = (size_t)(n0 + row) * K + k0 + cc * 8;
                CP_ASYNC16(ns + T_AH + so, Ah + ga);
                CP_ASYNC16(ns + T_AL + so, Al + ga);
                CP_ASYNC16(ns + T_BH + so, Bh + gb);
                CP_ASYNC16(ns + T_BL + so, Bl + gb);
            }
            CP_COMMIT();
            CP_WAIT1();
        } else {
            CP_WAIT0();
        }
        __syncthreads();
        #pragma unroll
        for (int kc = 0; kc < 4; kc++) {
            uint32_t ah[2][4], al[2][4];
            #pragma unroll
            for (int i = 0; i < 2; i++) {
                uint32_t ao = cs + (wm + (i << 4) + arow) * 144 + ((kc << 4) + ak) * 2;
                ldsm4(ao + T_AH, ah[i][0], ah[i][1], ah[i][2], ah[i][3]);
                ldsm4(ao + T_AL, al[i][0], al[i][1], al[i][2], al[i][3]);
            }
            #pragma unroll
            for (int jj = 0; jj < 4; jj++) {
                uint32_t bo = cs + (wn + (jj << 4) + brow) * 144 + ((kc << 4) + bk) * 2;
                uint32_t bh0, bh1, bh2, bh3, bl0, bl1, bl2, bl3;
                ldsm4(bo + T_BH, bh0, bh1, bh2, bh3);
                ldsm4(bo + T_BL, bl0, bl1, bl2, bl3);
                #pragma unroll
                for (int i = 0; i < 2; i++) {
                    mma_bf16(acc[i][2 * jj],     ah[i], bh0, bh1);
                    mma_bf16(acc[i][2 * jj],     ah[i], bl0, bl1);
                    mma_bf16(acc[i][2 * jj],     al[i], bh0, bh1);
                    mma_bf16(acc[i][2 * jj + 1], ah[i], bh2, bh3);
                    mma_bf16(acc[i][2 * jj + 1], ah[i], bl2, bl3);
                    mma_bf16(acc[i][2 * jj + 1], al[i], bh2, bh3);
                }
            }
        }
        __syncthreads();
    }

    const int g = lane >> 2, tg = (lane & 3) << 1;
    #pragma unroll
    for (int i = 0; i < 2; i++) {
        const int row0 = m0 + wm + (i << 4) + g;
        #pragma unroll
        for (int j = 0; j < 8; j++) {
            const int col = n0 + wn + (j << 3) + tg;
            float b0 = 0.f, b1 = 0.f;
            if (bias) { b0 = bias[col]; b1 = bias[col + 1]; }
            float v0 = acc[i][j][0] + b0, v1 = acc[i][j][1] + b1;
            float v2 = acc[i][j][2] + b0, v3 = acc[i][j][3] + b1;
            if (act) {
                v0 = 0.5f * v0 * (1.0f + erff(v0 * 0.70710678118654752f));
                v1 = 0.5f * v1 * (1.0f + erff(v1 * 0.70710678118654752f));
                v2 = 0.5f * v2 * (1.0f + erff(v2 * 0.70710678118654752f));
                v3 = 0.5f * v3 * (1.0f + erff(v3 * 0.70710678118654752f));
            }
            if (C) {
                *(float2*)(C + (size_t)row0 * Nt + col) = make_float2(v0, v1);
                *(float2*)(C + (size_t)(row0 + 8) * Nt + col) = make_float2(v2, v3);
            }
            if (Ch) {
                uint32_t h0, l0, h1, l1;
                splitf2(v0, v1, h0, l0);
                splitf2(v2, v3, h1, l1);
                *(uint32_t*)(Ch + (size_t)row0 * Nt + col) = h0;
                *(uint32_t*)(Ch + (size_t)(row0 + 8) * Nt + col) = h1;
                if (Cl) {
                    *(uint32_t*)(Cl + (size_t)row0 * Nt + col) = l0;
                    *(uint32_t*)(Cl + (size_t)(row0 + 8) * Nt + col) = l1;
                }
            }
        }
    }
}

// -------------------- GEMM NN (fp32, tiny: weight folding) --------------------
__global__ __launch_bounds__(256) void gemm_nn(
    float* __restrict__ C, const float* __restrict__ A, const float* __restrict__ B,
    int M, int N, int K)
{
    __shared__ float As[16][64];
    __shared__ float Bs[16][64];
    const int tid = threadIdx.x;
    const int tx = tid & 15, ty = tid >> 4;
    const int lr = tid >> 2, lc = (tid & 3) << 2;
    const int bkr = tid >> 4, bnc = (tid & 15) << 2;
    const float* Ab = A + (size_t)blockIdx.y * 64 * K;
    float acc[4][4] = {};
    for (int k0 = 0; k0 < K; k0 += 16) {
        float4 a4 = *(const float4*)(Ab + (size_t)lr * K + k0 + lc);
        float4 b4 = *(const float4*)(B + (size_t)(k0 + bkr) * N + blockIdx.x * 64 + bnc);
        __syncthreads();
        As[lc + 0][lr] = a4.x; As[lc + 1][lr] = a4.y; As[lc + 2][lr] = a4.z; As[lc + 3][lr] = a4.w;
        *(float4*)&Bs[bkr][bnc] = b4;
        __syncthreads();
        #pragma unroll
        for (int k = 0; k < 16; k++) {
            float4 av = *(const float4*)&As[k][ty << 2];
            float4 bv = *(const float4*)&Bs[k][tx << 2];
            float a[4] = {av.x, av.y, av.z, av.w};
            float b[4] = {bv.x, bv.y, bv.z, bv.w};
            #pragma unroll
            for (int i = 0; i < 4; i++)
                #pragma unroll
                for (int j = 0; j < 4; j++) acc[i][j] += a[i] * b[j];
        }
    }
    #pragma unroll
    for (int i = 0; i < 4; i++) {
        int m = blockIdx.y * 64 + (ty << 2) + i;
        #pragma unroll
        for (int j = 0; j < 4; j++)
            C[(size_t)m * N + blockIdx.x * 64 + (tx << 2) + j] = acc[i][j];
    }
}

// ==================== tensor-core flash attention (pre-split I/O) ====================
// Q/K pre-split bf16 hi/lo, V plain bf16. Output split bf16 hi/lo.
#define AQ_H 0
#define AQ_L 18432
#define AK_B(s) (36864 + (s) * 18432)
#define AVT  73728
#define AT_SMEM 82944

__global__ __launch_bounds__(256, 1) void attn_mma(
    bf16* __restrict__ Oh, bf16* __restrict__ Ol,
    const bf16* __restrict__ Qh, const bf16* __restrict__ Ql,
    const bf16* __restrict__ Kh, const bf16* __restrict__ Kl,
    const bf16* __restrict__ Vb)
{
    extern __shared__ char smem[];
    const uint32_t sb = smem_u32(smem);
    const int tid = threadIdx.x, wid = tid >> 5, lane = tid & 31;
    const int b = blockIdx.z, h = blockIdx.y;
    const int q0 = blockIdx.x * 128;
    const size_t tok0 = (size_t)b * SEQL;
    const int hc = h * 64;
    const int quad = lane >> 3, r = lane & 7;
    const int arow = ((quad & 1) << 3) + r, ak = (quad >> 1) << 3;
    const int brow = ((quad >> 1) << 3) + r, bk = (quad & 1) << 3;
    const int g = lane >> 2, tg = lane & 3;
    const int wq0 = wid << 4;

    // prologue: cp.async Q (hi+lo) and K tile 0 (hi+lo); prefetch V0 to regs
    {
        #pragma unroll
        for (int j = 0; j < 4; j++) {
            int ch = tid + (j << 8);
            int row = ch >> 3, cc = ch & 7;
            uint32_t so = row * 144 + cc * 16;
            size_t ga = (tok0 + q0 + row) * D + hc + cc * 8;
            CP_ASYNC16(sb + AQ_H + so, Qh + ga);
            CP_ASYNC16(sb + AQ_L + so, Ql + ga);
        }
        #pragma unroll
        for (int j = 0; j < 2; j++) {
            int ch = tid + (j << 8);
            int row = ch >> 3, cc = ch & 7;
            uint32_t so = row * 144 + cc * 16;
            size_t ga = (tok0 + row) * D + hc + cc * 8;
            CP_ASYNC16(sb + AK_B(0) + so, Kh + ga);
            CP_ASYNC16(sb + AK_B(0) + 9216 + so, Kl + ga);
        }
        CP_COMMIT();
    }
    uint4 vr[2];
    #pragma unroll
    for (int j = 0; j < 2; j++) {
        int ch = tid + (j << 8);
        int row = ch >> 3, cc = ch & 7;
        vr[j] = *(const uint4*)(Vb + (tok0 + row) * D + hc + cc * 8);
    }

    float o[8][4];
    #pragma unroll
    for (int j = 0; j < 8; j++)
        #pragma unroll
        for (int q = 0; q < 4; q++) o[j][q] = 0.f;
    float m0r = -1e30f, m1r = -1e30f, l0r = 0.f, l1r = 0.f;

    for (int kt = 0; kt < SEQL / 64; kt++) {
        const int s = kt & 1;
        if (kt + 1 < SEQL / 64) {
            const size_t kb = tok0 + (size_t)(kt + 1) * 64;
            #pragma unroll
            for (int j = 0; j < 2; j++) {
                int ch = tid + (j << 8);
                int row = ch >> 3, cc = ch & 7;
                uint32_t so = row * 144 + cc * 16;
                size_t ga = (kb + row) * D + hc + cc * 8;
                CP_ASYNC16(sb + AK_B(1 - s) + so, Kh + ga);
                CP_ASYNC16(sb + AK_B(1 - s) + 9216 + so, Kl + ga);
            }
            CP_COMMIT();
        }
        // V transpose STS from regs (VT free: prior iter ended with sync)
        #pragma unroll
        for (int j = 0; j < 2; j++) {
            int ch = tid + (j << 8);
            int row = ch >> 3, cc = ch & 7;
            const bf16* pv = (const bf16*)&vr[j];
            #pragma unroll
            for (int e = 0; e < 8; e++) {
                int d = cc * 8 + e;
                *(bf16*)(smem + AVT + d * 144 + row * 2) = pv[e];
            }
        }
        if (kt + 1 < SEQL / 64) { CP_WAIT1(); } else { CP_WAIT0(); }
        __syncthreads();
        if (kt + 1 < SEQL / 64) {
            const size_t kb = tok0 + (size_t)(kt + 1) * 64;
            #pragma unroll
            for (int j = 0; j < 2; j++) {
                int ch = tid + (j << 8);
                int row = ch >> 3, cc = ch & 7;
                vr[j] = *(const uint4*)(Vb + (kb + row) * D + hc + cc * 8);
            }
        }
        // S = Q @ K^T (3-term split-bf16)
        float sc[8][4];
        #pragma unroll
        for (int j = 0; j < 8; j++)
            #pragma unroll
            for (int q = 0; q < 4; q++) sc[j][q] = 0.f;
        #pragma unroll
        for (int kc = 0; kc < 4; kc++) {
            uint32_t ah[4], al[4];
            uint32_t ao = sb + (wq0 + arow) * 144 + ((kc << 4) + ak) * 2;
            ldsm4(ao + AQ_H, ah[0], ah[1], ah[2], ah[3]);
            ldsm4(ao + AQ_L, al[0], al[1], al[2], al[3]);
            #pragma unroll
            for (int jj = 0; jj < 4; jj++) {
                uint32_t bo = sb + AK_B(s) + ((jj << 4) + brow) * 144 + ((kc << 4) + bk) * 2;
                uint32_t bh0, bh1, bh2, bh3, bl0, bl1, bl2, bl3;
                ldsm4(bo, bh0, bh1, bh2, bh3);
                ldsm4(bo + 9216, bl0, bl1, bl2, bl3);
                mma_bf16(sc[2 * jj],     ah, bh0, bh1);
                mma_bf16(sc[2 * jj],     ah, bl0, bl1);
                mma_bf16(sc[2 * jj],     al, bh0, bh1);
                mma_bf16(sc[2 * jj + 1], ah, bh2, bh3);
                mma_bf16(sc[2 * jj + 1], ah, bl2, bl3);
                mma_bf16(sc[2 * jj + 1], al, bh2, bh3);
            }
        }
        // online softmax
        float mx0 = -1e30f, mx1 = -1e30f;
        #pragma unroll
        for (int j = 0; j < 8; j++) {
            sc[j][0] *= ATT_SCALE; sc[j][1] *= ATT_SCALE;
            sc[j][2] *= ATT_SCALE; sc[j][3] *= ATT_SCALE;
            mx0 = fmaxf(mx0, fmaxf(sc[j][0], sc[j][1]));
            mx1 = fmaxf(mx1, fmaxf(sc[j][2], sc[j][3]));
        }
        mx0 = fmaxf(mx0, __shfl_xor_sync(0xffffffffu, mx0, 1));
        mx0 = fmaxf(mx0, __shfl_xor_sync(0xffffffffu, mx0, 2));
        mx1 = fmaxf(mx1, __shfl_xor_sync(0xffffffffu, mx1, 1));
        mx1 = fmaxf(mx1, __shfl_xor_sync(0xffffffffu, mx1, 2));
        float mn0 = fmaxf(m0r, mx0), mn1 = fmaxf(m1r, mx1);
        float a0 = __expf(m0r - mn0), a1 = __expf(m1r - mn1);
        m0r = mn0; m1r = mn1;
        float rs0 = 0.f, rs1 = 0.f;
        #pragma unroll
        for (int j = 0; j < 8; j++) {
            sc[j][0] = __expf(sc[j][0] - mn0); sc[j][1] = __expf(sc[j][1] - mn0);
            sc[j][2] = __expf(sc[j][2] - mn1); sc[j][3] = __expf(sc[j][3] - mn1);
            rs0 += sc[j][0] + sc[j][1];
            rs1 += sc[j][2] + sc[j][3];
        }
        rs0 += __shfl_xor_sync(0xffffffffu, rs0, 1);
        rs0 += __shfl_xor_sync(0xffffffffu, rs0, 2);
        rs1 += __shfl_xor_sync(0xffffffffu, rs1, 1);
        rs1 += __shfl_xor_sync(0xffffffffu, rs1, 2);
        l0r = l0r * a0 + rs0;
        l1r = l1r * a1 + rs1;
        #pragma unroll
        for (int j = 0; j < 8; j++) {
            o[j][0] *= a0; o[j][1] *= a0; o[j][2] *= a1; o[j][3] *= a1;
        }
        // O += P @ V
        #pragma unroll
        for (int kk = 0; kk < 4; kk++) {
            uint32_t pa[4];
            __nv_bfloat162 t0 = __float22bfloat162_rn(make_float2(sc[2 * kk][0], sc[2 * kk][1]));
            __nv_bfloat162 t1 = __float22bfloat162_rn(make_float2(sc[2 * kk][2], sc[2 * kk][3]));
            __nv_bfloat162 t2 = __float22bfloat162_rn(make_float2(sc[2 * kk + 1][0], sc[2 * kk + 1][1]));
            __nv_bfloat162 t3 = __float22bfloat162_rn(make_float2(sc[2 * kk + 1][2], sc[2 * kk + 1][3]));
            pa[0] = *(uint32_t*)&t0; pa[1] = *(uint32_t*)&t1;
            pa[2] = *(uint32_t*)&t2; pa[3] = *(uint32_t*)&t3;
            #pragma unroll
            for (int jj = 0; jj < 4; jj++) {
                uint32_t bo = sb + AVT + ((jj << 4) + brow) * 144 + ((kk << 4) + bk) * 2;
                uint32_t b0, b1, b2, b3;
                ldsm4(bo, b0, b1, b2, b3);
                mma_bf16(o[2 * jj],     pa, b0, b1);
                mma_bf16(o[2 * jj + 1], pa, b2, b3);
            }
        }
        __syncthreads();
    }
    const float inv0 = 1.0f / l0r, inv1 = 1.0f / l1r;
    #pragma unroll
    for (int j = 0; j < 8; j++) {
        int col = hc + (j << 3) + (tg << 1);
        size_t r0 = (tok0 + q0 + wq0 + g) * D + col;
        size_t r1 = (tok0 + q0 + wq0 + g + 8) * D + col;
        uint32_t h0, l0, h1, l1;
        splitf2(o[j][0] * inv0, o[j][1] * inv0, h0, l0);
        splitf2(o[j][2] * inv1, o[j][3] * inv1, h1, l1);
        *(uint32_t*)(Oh + r0) = h0; *(uint32_t*)(Ol + r0) = l0;
        *(uint32_t*)(Oh + r1) = h1; *(uint32_t*)(Ol + r1) = l1;
    }
}

// -------------------- conv along feature dim -> split bf16 out --------------------
__global__ __launch_bounds__(128) void conv_row(
    bf16* __restrict__ outH, bf16* __restrict__ outL,
    const float* __restrict__ in, const float* __restrict__ w)
{
    __shared__ float rb[D];
    const int row = blockIdx.x, t = threadIdx.x;
    float4 v = *(const float4*)(in + (size_t)row * D + t * 4);
    *(float4*)&rb[t * 4] = v;
    __syncthreads();
    const float w0 = w[0], w1 = w[1], w2 = w[2];
    float y[4];
    #pragma unroll
    for (int i = 0; i < 4; i++) {
        int c = t * 4 + i;
        float xm = (c > 0) ? rb[c - 1] : 0.f;
        float xp = (c < D - 1) ? rb[c + 1] : 0.f;
        y[i] = w0 * xm + w1 * rb[c] + w2 * xp;
    }
    uint32_t h0, l0, h1, l1;
    splitf2(y[0], y[1], h0, l0);
    splitf2(y[2], y[3], h1, l1);
    *(uint2*)(outH + (size_t)row * D + t * 4) = make_uint2(h0, h1);
    *(uint2*)(outL + (size_t)row * D + t * 4) = make_uint2(l0, l1);
}

// -------------------- LN(a+b)*g+be; fp32 + optional split bf16 + hn --------------------
__global__ __launch_bounds__(128) void ln_kernel(
    float* __restrict__ out, bf16* __restrict__ outH, bf16* __restrict__ outL,
    const float* __restrict__ a, const float* __restrict__ b,
    const float* __restrict__ g, const float* __restrict__ be,
    float* __restrict__ hn_out, int do_hn)
{
    __shared__ float sh[8];
    const int row = blockIdx.x, t = threadIdx.x;
    float4 av = *(const float4*)(a + (size_t)row * D + t * 4);
    float4 bv = *(const float4*)(b + (size_t)row * D + t * 4);
    float v[4] = {av.x + bv.x, av.y + bv.y, av.z + bv.z, av.w + bv.w};
    float s = v[0] + v[1] + v[2] + v[3];
    float s2 = v[0] * v[0] + v[1] * v[1] + v[2] * v[2] + v[3] * v[3];
    #pragma unroll
    for (int off = 16; off; off >>= 1) {
        s += __shfl_xor_sync(0xffffffffu, s, off);
        s2 += __shfl_xor_sync(0xffffffffu, s2, off);
    }
    if ((t & 31) == 0) { sh[t >> 5] = s; sh[4 + (t >> 5)] = s2; }
    __syncthreads();
    s = sh[0] + sh[1] + sh[2] + sh[3];
    s2 = sh[4] + sh[5] + sh[6] + sh[7];
    const float mean = s * (1.0f / D);
    const float rstd = rsqrtf(s2 * (1.0f / D) - mean * mean + 1e-5f);
    float4 gv = *(const float4*)(g + t * 4);
    float4 bev = *(const float4*)(be + t * 4);
    float y[4];
    y[0] = (v[0] - mean) * rstd * gv.x + bev.x;
    y[1] = (v[1] - mean) * rstd * gv.y + bev.y;
    y[2] = (v[2] - mean) * rstd * gv.z + bev.z;
    y[3] = (v[3] - mean) * rstd * gv.w + bev.w;
    *(float4*)(out + (size_t)row * D + t * 4) = make_float4(y[0], y[1], y[2], y[3]);
    if (outH) {
        uint32_t h0, l0, h1, l1;
        splitf2(y[0], y[1], h0, l0);
        splitf2(y[2], y[3], h1, l1);
        *(uint2*)(outH + (size_t)row * D + t * 4) = make_uint2(h0, h1);
        *(uint2*)(outL + (size_t)row * D + t * 4) = make_uint2(l0, l1);
    }
    if (do_hn && (row & (SEQL - 1)) == SEQL - 1)
        *(float4*)(hn_out + (size_t)(row >> 10) * D + t * 4) = av;
}

// -------------------- fused LN1 + conv2 -> x1 fp32, x2c split bf16 --------------------
__global__ __launch_bounds__(128) void ln_conv_kernel(
    float* __restrict__ x1, bf16* __restrict__ x2cH, bf16* __restrict__ x2cL,
    const float* __restrict__ a, const float* __restrict__ b,
    const float* __restrict__ g, const float* __restrict__ be,
    const float* __restrict__ w)
{
    __shared__ float sh[8];
    __shared__ float rb[D];
    const int row = blockIdx.x, t = threadIdx.x;
    float4 av = *(const float4*)(a + (size_t)row * D + t * 4);
    float4 bv = *(const float4*)(b + (size_t)row * D + t * 4);
    float v[4] = {av.x + bv.x, av.y + bv.y, av.z + bv.z, av.w + bv.w};
    float s = v[0] + v[1] + v[2] + v[3];
    float s2 = v[0] * v[0] + v[1] * v[1] + v[2] * v[2] + v[3] * v[3];
    #pragma unroll
    for (int off = 16; off; off >>= 1) {
        s += __shfl_xor_sync(0xffffffffu, s, off);
        s2 += __shfl_xor_sync(0xffffffffu, s2, off);
    }
    if ((t & 31) == 0) { sh[t >> 5] = s; sh[4 + (t >> 5)] = s2; }
    __syncthreads();
    s = sh[0] + sh[1] + sh[2] + sh[3];
    s2 = sh[4] + sh[5] + sh[6] + sh[7];
    const float mean = s * (1.0f / D);
    const float rstd = rsqrtf(s2 * (1.0f / D) - mean * mean + 1e-5f);
    float4 gv = *(const float4*)(g + t * 4);
    float4 bev = *(const float4*)(be + t * 4);
    float y[4];
    y[0] = (v[0] - mean) * rstd * gv.x + bev.x;
    y[1] = (v[1] - mean) * rstd * gv.y + bev.y;
    y[2] = (v[2] - mean) * rstd * gv.z + bev.z;
    y[3] = (v[3] - mean) * rstd * gv.w + bev.w;
    *(float4*)&rb[t * 4] = make_float4(y[0], y[1], y[2], y[3]);
    *(float4*)(x1 + (size_t)row * D + t * 4) = make_float4(y[0], y[1], y[2], y[3]);
    __syncthreads();
    const float w0 = w[0], w1 = w[1], w2 = w[2];
    float z[4];
    #pragma unroll
    for (int i = 0; i < 4; i++) {
        int c = t * 4 + i;
        float xm = (c > 0) ? rb[c - 1] : 0.f;
        float xp = (c < D - 1) ? rb[c + 1] : 0.f;
        z[i] = w0 * xm + w1 * rb[c] + w2 * xp;
    }
    uint32_t h0, l0, h1, l1;
    splitf2(z[0], z[1], h0, l0);
    splitf2(z[2], z[3], h1, l1);
    *(uint2*)(x2cH + (size_t)row * D + t * 4) = make_uint2(h0, h1);
    *(uint2*)(x2cL + (size_t)row * D + t * 4) = make_uint2(l0, l1);
}

// -------------------- launch --------------------
extern "C" void kernel_launch(void* const* d_in, const int* in_sizes, int n_in,
                              void* d_out, int out_size)
{
    const float* input   = (const float*)d_in[0];
    const float* wq_c    = (const float*)d_in[3];
    const float* fc_c    = (const float*)d_in[5];
    const float* wq_g    = (const float*)d_in[6];
    const float* wk_g    = (const float*)d_in[7];
    const float* fc_g    = (const float*)d_in[8];
    const float* wq_x    = (const float*)d_in[9];
    const float* fc_x    = (const float*)d_in[11];
    const float* conv1_w = (const float*)d_in[12];
    const float* conv2_w = (const float*)d_in[13];
    const float* ln1_g = (const float*)d_in[14];
    const float* ln1_b = (const float*)d_in[15];
    const float* ln2_g = (const float*)d_in[16];
    const float* ln2_b = (const float*)d_in[17];
    const float* ln3_g = (const float*)d_in[18];
    const float* ln3_b = (const float*)d_in[19];
    const float* ln4_g = (const float*)d_in[20];
    const float* ln4_b = (const float*)d_in[21];
    const float* mlp_w1 = (const float*)d_in[22];
    const float* mlp_b1 = (const float*)d_in[23];
    const float* mlp_w2 = (const float*)d_in[24];
    const float* mlp_b2 = (const float*)d_in[25];

    float *M1, *M3, *B0, *B1, *B2, *B3, *B4;
    bf16 *Wh, *Wl, *XH, *XL, *C1H, *C1L, *QH, *QL, *KH, *KL, *VB;
    bf16 *ATH, *ATL, *X2CH, *X2CL, *X2H, *X2L, *X3H, *X3L, *HIDH, *HIDL;
    cudaGetSymbolAddress((void**)&M1, d_M1);
    cudaGetSymbolAddress((void**)&M3, d_M3);
    cudaGetSymbolAddress((void**)&B0, d_B0);
    cudaGetSymbolAddress((void**)&B1, d_B1);
    cudaGetSymbolAddress((void**)&B2, d_B2);
    cudaGetSymbolAddress((void**)&B3, d_B3);
    cudaGetSymbolAddress((void**)&B4, d_B4);
    cudaGetSymbolAddress((void**)&Wh, d_Wh);
    cudaGetSymbolAddress((void**)&Wl, d_Wl);
    cudaGetSymbolAddress((void**)&XH, d_XH);
    cudaGetSymbolAddress((void**)&XL, d_XL);
    cudaGetSymbolAddress((void**)&C1H, d_C1H);
    cudaGetSymbolAddress((void**)&C1L, d_C1L);
    cudaGetSymbolAddress((void**)&QH, d_QH);
    cudaGetSymbolAddress((void**)&QL, d_QL);
    cudaGetSymbolAddress((void**)&KH, d_KH);
    cudaGetSymbolAddress((void**)&KL, d_KL);
    cudaGetSymbolAddress((void**)&VB, d_VB);
    cudaGetSymbolAddress((void**)&ATH, d_ATH);
    cudaGetSymbolAddress((void**)&ATL, d_ATL);
    cudaGetSymbolAddress((void**)&X2CH, d_X2CH);
    cudaGetSymbolAddress((void**)&X2CL, d_X2CL);
    cudaGetSymbolAddress((void**)&X2H, d_X2H);
    cudaGetSymbolAddress((void**)&X2L, d_X2L);
    cudaGetSymbolAddress((void**)&X3H, d_X3H);
    cudaGetSymbolAddress((void**)&X3L, d_X3L);
    cudaGetSymbolAddress((void**)&HIDH, d_HIDH);
    cudaGetSymbolAddress((void**)&HIDL, d_HIDL);

    cudaFuncSetAttribute(mma_gemm, cudaFuncAttributeMaxDynamicSharedMemorySize, TCG_SMEM);
    cudaFuncSetAttribute(attn_mma, cudaFuncAttributeMaxDynamicSharedMemorySize, AT_SMEM);

    float* outp = (float*)d_out;
    const size_t out_main = (size_t)N_TOK * D;
    float* hnp = outp + out_main;
    int do_hn = (out_size >= (int)(out_main + BSZ * D)) ? 1 : 0;
    if (!do_hn) hnp = outp;

    const dim3 blk(256);
    const dim3 tg512(D / 128, N_TOK / 128);
    const dim3 tg2048(DFF / 128, N_TOK / 128);
    const dim3 gW(D / 64, D / 64);
    const int nW512 = D * D / 1024;
    const int nW2048 = D * DFF / 1024;
    const int nX = N_TOK * D / 1024;

    // weight folding + splits
    gemm_nn<<<gW, blk>>>(M1, fc_c, wq_c, D, D, D);
    gemm_nn<<<gW, blk>>>(M3, fc_x, wq_x, D, D, D);
    split_w<<<nW512, blk>>>(Wh + OFF_WKG, Wl + OFF_WKG, wk_g, D * D);
    split_w<<<nW512, blk>>>(Wh + OFF_WQG, Wl + OFF_WQG, wq_g, D * D);
    split_w<<<nW512, blk>>>(Wh + OFF_M1,  Wl + OFF_M1,  M1, D * D);
    split_w<<<nW512, blk>>>(Wh + OFF_FCG, Wl + OFF_FCG, fc_g, D * D);
    split_w<<<nW512, blk>>>(Wh + OFF_M3,  Wl + OFF_M3,  M3, D * D);
    split_w<<<nW2048, blk>>>(Wh + OFF_W1, Wl + OFF_W1, mlp_w1, D * DFF);
    split_w<<<nW2048, blk>>>(Wh + OFF_W2, Wl + OFF_W2, mlp_w2, D * DFF);
    split_w<<<nX, blk>>>(XH, XL, input, N_TOK * D);

    // Kg (split out), Vg (plain bf16 out)
    mma_gemm<<<tg512, blk, TCG_SMEM>>>(nullptr, KH, KL, XH, XL, Wh + OFF_WKG, Wl + OFF_WKG, N_TOK, D, D, nullptr, 0);
    mma_gemm<<<tg512, blk, TCG_SMEM>>>(nullptr, VB, nullptr, XH, XL, Wh + OFF_WQG, Wl + OFF_WQG, N_TOK, D, D, nullptr, 0);

    // conv1 -> u -> ln1+conv2
    conv_row<<<N_TOK, 128>>>(C1H, C1L, input, conv1_w);
    mma_gemm<<<tg512, blk, TCG_SMEM>>>(B1, nullptr, nullptr, C1H, C1L, Wh + OFF_M1, Wl + OFF_M1, N_TOK, D, D, nullptr, 0);
    ln_conv_kernel<<<N_TOK, 128>>>(B2, X2CH, X2CL, B1, input, ln1_g, ln1_b, conv2_w);

    // Q -> attention -> fc_g -> ln2
    mma_gemm<<<tg512, blk, TCG_SMEM>>>(nullptr, QH, QL, X2CH, X2CL, Wh + OFF_WQG, Wl + OFF_WQG, N_TOK, D, D, nullptr, 0);
    attn_mma<<<dim3(SEQL / 128, 8, BSZ), blk, AT_SMEM>>>(ATH, ATL, QH, QL, KH, KL, VB);
    mma_gemm<<<tg512, blk, TCG_SMEM>>>(B0, nullptr, nullptr, ATH, ATL, Wh + OFF_FCG, Wl + OFF_FCG, N_TOK, D, D, nullptr, 0);
    ln_kernel<<<N_TOK, 128>>>(B3, X2H, X2L, B0, B2, ln2_g, ln2_b, hnp, 0);

    // h -> ln3 (+hn)
    mma_gemm<<<tg512, blk, TCG_SMEM>>>(B1, nullptr, nullptr, X2H, X2L, Wh + OFF_M3, Wl + OFF_M3, N_TOK, D, D, nullptr, 0);
    ln_kernel<<<N_TOK, 128>>>(B4, X3H, X3L, B1, B3, ln3_g, ln3_b, hnp, do_hn);

    // MLP
    mma_gemm<<<tg2048, blk, TCG_SMEM>>>(nullptr, HIDH, HIDL, X3H, X3L, Wh + OFF_W1, Wl + OFF_W1, N_TOK, DFF, D, mlp_b1, 1);
    mma_gemm<<<tg512, blk, TCG_SMEM>>>(B0, nullptr, nullptr, HIDH, HIDL, Wh + OFF_W2, Wl + OFF_W2, N_TOK, D, DFF, mlp_b2, 0);
    ln_kernel<<<N_TOK, 128>>>(outp, nullptr, nullptr, B0, B4, ln4_g, ln4_b, hnp, 0);
}

// round 9
// speedup vs baseline: 1.0512x; 1.0512x over previous
#include <cuda_runtime.h>
#include <cuda_bf16.h>
#include <math.h>
#include <stdint.h>

#define N_TOK 16384
#define D 512
#define SEQL 1024
#define BSZ 16
#define DFF 2048
#define ATT_SCALE 0.125f

typedef __nv_bfloat16 bf16;

// -------------------- fp32 scratch --------------------
__device__ float d_M1[D * D];
__device__ float d_M3[D * D];
__device__ float d_B0[(size_t)N_TOK * D];
__device__ float d_B1[(size_t)N_TOK * D];
__device__ float d_B2[(size_t)N_TOK * D];
__device__ float d_B3[(size_t)N_TOK * D];
__device__ float d_B4[(size_t)N_TOK * D];

// -------------------- split-bf16 weights --------------------
#define OFF_WKG 0
#define OFF_WQG 262144
#define OFF_M1  524288
#define OFF_FCG 786432
#define OFF_M3  1048576
#define OFF_W1  1310720
#define OFF_W2  2359296
#define W_TOTAL 3407872
__device__ bf16 d_Wh[W_TOTAL];
__device__ bf16 d_Wl[W_TOTAL];

// -------------------- split-bf16 activations --------------------
#define ACT_N ((size_t)N_TOK * D)
__device__ bf16 d_XH[ACT_N],   d_XL[ACT_N];
__device__ bf16 d_C1H[ACT_N],  d_C1L[ACT_N];
__device__ bf16 d_QH[ACT_N],   d_QL[ACT_N];
__device__ bf16 d_KH[ACT_N],   d_KL[ACT_N];
__device__ bf16 d_VB[ACT_N];
__device__ bf16 d_ATH[ACT_N],  d_ATL[ACT_N];
__device__ bf16 d_X2CH[ACT_N], d_X2CL[ACT_N];
__device__ bf16 d_X2H[ACT_N],  d_X2L[ACT_N];
__device__ bf16 d_X3H[ACT_N],  d_X3L[ACT_N];
__device__ bf16 d_HIDH[(size_t)N_TOK * DFF], d_HIDL[(size_t)N_TOK * DFF];

// ==================== helpers ====================
__device__ __forceinline__ uint32_t smem_u32(const void* p) {
    uint32_t a;
    asm("{ .reg .u64 t; cvta.to.shared.u64 t, %1; cvt.u32.u64 %0, t; }" : "=r"(a) : "l"(p));
    return a;
}
__device__ __forceinline__ void ldsm4(uint32_t addr, uint32_t& r0, uint32_t& r1, uint32_t& r2, uint32_t& r3) {
    asm volatile("ldmatrix.sync.aligned.m8n8.x4.shared.b16 {%0,%1,%2,%3}, [%4];"
                 : "=r"(r0), "=r"(r1), "=r"(r2), "=r"(r3) : "r"(addr));
}
__device__ __forceinline__ void mma_bf16(float c[4], const uint32_t a[4], uint32_t b0, uint32_t b1) {
    asm volatile(
        "mma.sync.aligned.m16n8k16.row.col.f32.bf16.bf16.f32 "
        "{%0,%1,%2,%3}, {%4,%5,%6,%7}, {%8,%9}, {%0,%1,%2,%3};"
        : "+f"(c[0]), "+f"(c[1]), "+f"(c[2]), "+f"(c[3])
        : "r"(a[0]), "r"(a[1]), "r"(a[2]), "r"(a[3]), "r"(b0), "r"(b1));
}
__device__ __forceinline__ void splitf2(float x, float y, uint32_t& h, uint32_t& l) {
    __nv_bfloat162 hh = __float22bfloat162_rn(make_float2(x, y));
    float2 hf = __bfloat1622float2(hh);
    __nv_bfloat162 ll = __float22bfloat162_rn(make_float2(x - hf.x, y - hf.y));
    h = *(uint32_t*)&hh; l = *(uint32_t*)&ll;
}
__device__ __forceinline__ void split2(float4 v, uint2& hi, uint2& lo) {
    uint32_t h0, l0, h1, l1;
    splitf2(v.x, v.y, h0, l0);
    splitf2(v.z, v.w, h1, l1);
    hi = make_uint2(h0, h1);
    lo = make_uint2(l0, l1);
}
#define CP_ASYNC16(dst, src) asm volatile("cp.async.cg.shared.global [%0], [%1], 16;" :: "r"(dst), "l"(src) : "memory")
#define CP_COMMIT()          asm volatile("cp.async.commit_group;" ::: "memory")
#define CP_WAIT0()           asm volatile("cp.async.wait_group 0;" ::: "memory")
#define CP_WAIT1()           asm volatile("cp.async.wait_group 1;" ::: "memory")

// -------------------- generic fp32 -> bf16 hi/lo split --------------------
__global__ __launch_bounds__(256) void split_w(
    bf16* __restrict__ H, bf16* __restrict__ L, const float* __restrict__ W, int n)
{
    int i = (blockIdx.x * 256 + threadIdx.x) * 4;
    if (i < n) {
        float4 v = *(const float4*)(W + i);
        uint2 h, l; split2(v, h, l);
        *(uint2*)(H + i) = h;
        *(uint2*)(L + i) = l;
    }
}

// ==================== single-stage streamed split-bf16 mma GEMM, 2 CTAs/SM ====================
#define T_AH 0
#define T_AL 18432
#define T_BH 36864
#define T_BL 55296
#define TCG_SMEM 73728

__global__ __launch_bounds__(256, 2) void mma_gemm(
    float* __restrict__ C, bf16* __restrict__ Ch, bf16* __restrict__ Cl,
    const bf16* __restrict__ Ah, const bf16* __restrict__ Al,
    const bf16* __restrict__ Bh, const bf16* __restrict__ Bl,
    int M, int Nt, int K, const float* __restrict__ bias, int act)
{
    extern __shared__ char smem[];
    const uint32_t sb = smem_u32(smem);
    const int tid = threadIdx.x, wid = tid >> 5, lane = tid & 31;
    const int m0 = blockIdx.y * 128, n0 = blockIdx.x * 128;
    const int wm = (wid & 3) << 5;
    const int wn = (wid >> 2) << 6;
    const int quad = lane >> 3, r = lane & 7;
    const int arow = ((quad & 1) << 3) + r, ak = (quad >> 1) << 3;
    const int brow = ((quad >> 1) << 3) + r, bk = (quad & 1) << 3;

    float acc[2][8][4];
    #pragma unroll
    for (int i = 0; i < 2; i++)
        #pragma unroll
        for (int j = 0; j < 8; j++)
            #pragma unroll
            for (int q = 0; q < 4; q++) acc[i][j][q] = 0.f;

    const int nit = K >> 6;

    // prologue: fill the single stage
    #pragma unroll
    for (int j = 0; j < 4; j++) {
        int ch = tid + (j << 8);
        int row = ch >> 3, cc = ch & 7;
        uint32_t so = row * 144 + cc * 16;
        size_t ga = (size_t)(m0 + row) * K + cc * 8;
        size_t gb = (size_t)(n0 + row) * K + cc * 8;
        CP_ASYNC16(sb + T_AH + so, Ah + ga);
        CP_ASYNC16(sb + T_AL + so, Al + ga);
        CP_ASYNC16(sb + T_BH + so, Bh + gb);
        CP_ASYNC16(sb + T_BL + so, Bl + gb);
    }
    CP_COMMIT();

    for (int it = 0; it < nit; it++) {
        CP_WAIT0();
        __syncthreads();
        #pragma unroll
        for (int kc = 0; kc < 4; kc++) {
            uint32_t ah[2][4], al[2][4];
            #pragma unroll
            for (int i = 0; i < 2; i++) {
                uint32_t ao = sb + (wm + (i << 4) + arow) * 144 + ((kc << 4) + ak) * 2;
                ldsm4(ao + T_AH, ah[i][0], ah[i][1], ah[i][2], ah[i][3]);
                ldsm4(ao + T_AL, al[i][0], al[i][1], al[i][2], al[i][3]);
            }
            #pragma unroll
            for (int jj = 0; jj < 4; jj++) {
                uint32_t bo = sb + (wn + (jj << 4) + brow) * 144 + ((kc << 4) + bk) * 2;
                uint32_t bh0, bh1, bh2, bh3, bl0, bl1, bl2, bl3;
                ldsm4(bo + T_BH, bh0, bh1, bh2, bh3);
                ldsm4(bo + T_BL, bl0, bl1, bl2, bl3);
                #pragma unroll
                for (int i = 0; i < 2; i++) {
                    mma_bf16(acc[i][2 * jj],     ah[i], bh0, bh1);
                    mma_bf16(acc[i][2 * jj],     ah[i], bl0, bl1);
                    mma_bf16(acc[i][2 * jj],     al[i], bh0, bh1);
                    mma_bf16(acc[i][2 * jj + 1], ah[i], bh2, bh3);
                    mma_bf16(acc[i][2 * jj + 1], ah[i], bl2, bl3);
                    mma_bf16(acc[i][2 * jj + 1], al[i], bh2, bh3);
                }
            }
        }
        __syncthreads();
        if (it + 1 < nit) {
            const int k0 = (it + 1) << 6;
            #pragma unroll
            for (int j = 0; j < 4; j++) {
                int ch = tid + (j << 8);
                int row = ch >> 3, cc = ch & 7;
                uint32_t so = row * 144 + cc * 16;
                size_t ga = (size_t)(m0 + row) * K + k0 + cc * 8;
                size_t gb = (size_t)(n0 + row) * K + k0 + cc * 8;
                CP_ASYNC16(sb + T_AH + so, Ah + ga);
                CP_ASYNC16(sb + T_AL + so, Al + ga);
                CP_ASYNC16(sb + T_BH + so, Bh + gb);
                CP_ASYNC16(sb + T_BL + so, Bl + gb);
            }
            CP_COMMIT();
        }
    }

    const int g = lane >> 2, tg = (lane & 3) << 1;
    #pragma unroll
    for (int i = 0; i < 2; i++) {
        const int row0 = m0 + wm + (i << 4) + g;
        #pragma unroll
        for (int j = 0; j < 8; j++) {
            const int col = n0 + wn + (j << 3) + tg;
            float b0 = 0.f, b1 = 0.f;
            if (bias) { b0 = bias[col]; b1 = bias[col + 1]; }
            float v0 = acc[i][j][0] + b0, v1 = acc[i][j][1] + b1;
            float v2 = acc[i][j][2] + b0, v3 = acc[i][j][3] + b1;
            if (act) {
                v0 = 0.5f * v0 * (1.0f + erff(v0 * 0.70710678118654752f));
                v1 = 0.5f * v1 * (1.0f + erff(v1 * 0.70710678118654752f));
                v2 = 0.5f * v2 * (1.0f + erff(v2 * 0.70710678118654752f));
                v3 = 0.5f * v3 * (1.0f + erff(v3 * 0.70710678118654752f));
            }
            if (C) {
                *(float2*)(C + (size_t)row0 * Nt + col) = make_float2(v0, v1);
                *(float2*)(C + (size_t)(row0 + 8) * Nt + col) = make_float2(v2, v3);
            }
            if (Ch) {
                uint32_t h0, l0, h1, l1;
                splitf2(v0, v1, h0, l0);
                splitf2(v2, v3, h1, l1);
                *(uint32_t*)(Ch + (size_t)row0 * Nt + col) = h0;
                *(uint32_t*)(Ch + (size_t)(row0 + 8) * Nt + col) = h1;
                if (Cl) {
                    *(uint32_t*)(Cl + (size_t)row0 * Nt + col) = l0;
                    *(uint32_t*)(Cl + (size_t)(row0 + 8) * Nt + col) = l1;
                }
            }
        }
    }
}

// -------------------- GEMM NN (fp32, tiny: weight folding) --------------------
__global__ __launch_bounds__(256) void gemm_nn(
    float* __restrict__ C, const float* __restrict__ A, const float* __restrict__ B,
    int M, int N, int K)
{
    __shared__ float As[16][64];
    __shared__ float Bs[16][64];
    const int tid = threadIdx.x;
    const int tx = tid & 15, ty = tid >> 4;
    const int lr = tid >> 2, lc = (tid & 3) << 2;
    const int bkr = tid >> 4, bnc = (tid & 15) << 2;
    const float* Ab = A + (size_t)blockIdx.y * 64 * K;
    float acc[4][4] = {};
    for (int k0 = 0; k0 < K; k0 += 16) {
        float4 a4 = *(const float4*)(Ab + (size_t)lr * K + k0 + lc);
        float4 b4 = *(const float4*)(B + (size_t)(k0 + bkr) * N + blockIdx.x * 64 + bnc);
        __syncthreads();
        As[lc + 0][lr] = a4.x; As[lc + 1][lr] = a4.y; As[lc + 2][lr] = a4.z; As[lc + 3][lr] = a4.w;
        *(float4*)&Bs[bkr][bnc] = b4;
        __syncthreads();
        #pragma unroll
        for (int k = 0; k < 16; k++) {
            float4 av = *(const float4*)&As[k][ty << 2];
            float4 bv = *(const float4*)&Bs[k][tx << 2];
            float a[4] = {av.x, av.y, av.z, av.w};
            float b[4] = {bv.x, bv.y, bv.z, bv.w};
            #pragma unroll
            for (int i = 0; i < 4; i++)
                #pragma unroll
                for (int j = 0; j < 4; j++) acc[i][j] += a[i] * b[j];
        }
    }
    #pragma unroll
    for (int i = 0; i < 4; i++) {
        int m = blockIdx.y * 64 + (ty << 2) + i;
        #pragma unroll
        for (int j = 0; j < 4; j++)
            C[(size_t)m * N + blockIdx.x * 64 + (tx << 2) + j] = acc[i][j];
    }
}

// ==================== tensor-core flash attention (unchanged from R7) ====================
#define AQ_H 0
#define AQ_L 18432
#define AK_B(s) (36864 + (s) * 18432)
#define AVT  73728
#define AT_SMEM 82944

__global__ __launch_bounds__(256, 1) void attn_mma(
    bf16* __restrict__ Oh, bf16* __restrict__ Ol,
    const bf16* __restrict__ Qh, const bf16* __restrict__ Ql,
    const bf16* __restrict__ Kh, const bf16* __restrict__ Kl,
    const bf16* __restrict__ Vb)
{
    extern __shared__ char smem[];
    const uint32_t sb = smem_u32(smem);
    const int tid = threadIdx.x, wid = tid >> 5, lane = tid & 31;
    const int b = blockIdx.z, h = blockIdx.y;
    const int q0 = blockIdx.x * 128;
    const size_t tok0 = (size_t)b * SEQL;
    const int hc = h * 64;
    const int quad = lane >> 3, r = lane & 7;
    const int arow = ((quad & 1) << 3) + r, ak = (quad >> 1) << 3;
    const int brow = ((quad >> 1) << 3) + r, bk = (quad & 1) << 3;
    const int g = lane >> 2, tg = lane & 3;
    const int wq0 = wid << 4;

    {
        #pragma unroll
        for (int j = 0; j < 4; j++) {
            int ch = tid + (j << 8);
            int row = ch >> 3, cc = ch & 7;
            uint32_t so = row * 144 + cc * 16;
            size_t ga = (tok0 + q0 + row) * D + hc + cc * 8;
            CP_ASYNC16(sb + AQ_H + so, Qh + ga);
            CP_ASYNC16(sb + AQ_L + so, Ql + ga);
        }
        #pragma unroll
        for (int j = 0; j < 2; j++) {
            int ch = tid + (j << 8);
            int row = ch >> 3, cc = ch & 7;
            uint32_t so = row * 144 + cc * 16;
            size_t ga = (tok0 + row) * D + hc + cc * 8;
            CP_ASYNC16(sb + AK_B(0) + so, Kh + ga);
            CP_ASYNC16(sb + AK_B(0) + 9216 + so, Kl + ga);
        }
        CP_COMMIT();
    }
    uint4 vr[2];
    #pragma unroll
    for (int j = 0; j < 2; j++) {
        int ch = tid + (j << 8);
        int row = ch >> 3, cc = ch & 7;
        vr[j] = *(const uint4*)(Vb + (tok0 + row) * D + hc + cc * 8);
    }

    float o[8][4];
    #pragma unroll
    for (int j = 0; j < 8; j++)
        #pragma unroll
        for (int q = 0; q < 4; q++) o[j][q] = 0.f;
    float m0r = -1e30f, m1r = -1e30f, l0r = 0.f, l1r = 0.f;

    for (int kt = 0; kt < SEQL / 64; kt++) {
        const int s = kt & 1;
        if (kt + 1 < SEQL / 64) {
            const size_t kb = tok0 + (size_t)(kt + 1) * 64;
            #pragma unroll
            for (int j = 0; j < 2; j++) {
                int ch = tid + (j << 8);
                int row = ch >> 3, cc = ch & 7;
                uint32_t so = row * 144 + cc * 16;
                size_t ga = (kb + row) * D + hc + cc * 8;
                CP_ASYNC16(sb + AK_B(1 - s) + so, Kh + ga);
                CP_ASYNC16(sb + AK_B(1 - s) + 9216 + so, Kl + ga);
            }
            CP_COMMIT();
        }
        #pragma unroll
        for (int j = 0; j < 2; j++) {
            int ch = tid + (j << 8);
            int row = ch >> 3, cc = ch & 7;
            const bf16* pv = (const bf16*)&vr[j];
            #pragma unroll
            for (int e = 0; e < 8; e++) {
                int d = cc * 8 + e;
                *(bf16*)(smem + AVT + d * 144 + row * 2) = pv[e];
            }
        }
        if (kt + 1 < SEQL / 64) { CP_WAIT1(); } else { CP_WAIT0(); }
        __syncthreads();
        if (kt + 1 < SEQL / 64) {
            const size_t kb = tok0 + (size_t)(kt + 1) * 64;
            #pragma unroll
            for (int j = 0; j < 2; j++) {
                int ch = tid + (j << 8);
                int row = ch >> 3, cc = ch & 7;
                vr[j] = *(const uint4*)(Vb + (kb + row) * D + hc + cc * 8);
            }
        }
        float sc[8][4];
        #pragma unroll
        for (int j = 0; j < 8; j++)
            #pragma unroll
            for (int q = 0; q < 4; q++) sc[j][q] = 0.f;
        #pragma unroll
        for (int kc = 0; kc < 4; kc++) {
            uint32_t ah[4], al[4];
            uint32_t ao = sb + (wq0 + arow) * 144 + ((kc << 4) + ak) * 2;
            ldsm4(ao + AQ_H, ah[0], ah[1], ah[2], ah[3]);
            ldsm4(ao + AQ_L, al[0], al[1], al[2], al[3]);
            #pragma unroll
            for (int jj = 0; jj < 4; jj++) {
                uint32_t bo = sb + AK_B(s) + ((jj << 4) + brow) * 144 + ((kc << 4) + bk) * 2;
                uint32_t bh0, bh1, bh2, bh3, bl0, bl1, bl2, bl3;
                ldsm4(bo, bh0, bh1, bh2, bh3);
                ldsm4(bo + 9216, bl0, bl1, bl2, bl3);
                mma_bf16(sc[2 * jj],     ah, bh0, bh1);
                mma_bf16(sc[2 * jj],     ah, bl0, bl1);
                mma_bf16(sc[2 * jj],     al, bh0, bh1);
                mma_bf16(sc[2 * jj + 1], ah, bh2, bh3);
                mma_bf16(sc[2 * jj + 1], ah, bl2, bl3);
                mma_bf16(sc[2 * jj + 1], al, bh2, bh3);
            }
        }
        float mx0 = -1e30f, mx1 = -1e30f;
        #pragma unroll
        for (int j = 0; j < 8; j++) {
            sc[j][0] *= ATT_SCALE; sc[j][1] *= ATT_SCALE;
            sc[j][2] *= ATT_SCALE; sc[j][3] *= ATT_SCALE;
            mx0 = fmaxf(mx0, fmaxf(sc[j][0], sc[j][1]));
            mx1 = fmaxf(mx1, fmaxf(sc[j][2], sc[j][3]));
        }
        mx0 = fmaxf(mx0, __shfl_xor_sync(0xffffffffu, mx0, 1));
        mx0 = fmaxf(mx0, __shfl_xor_sync(0xffffffffu, mx0, 2));
        mx1 = fmaxf(mx1, __shfl_xor_sync(0xffffffffu, mx1, 1));
        mx1 = fmaxf(mx1, __shfl_xor_sync(0xffffffffu, mx1, 2));
        float mn0 = fmaxf(m0r, mx0), mn1 = fmaxf(m1r, mx1);
        float a0 = __expf(m0r - mn0), a1 = __expf(m1r - mn1);
        m0r = mn0; m1r = mn1;
        float rs0 = 0.f, rs1 = 0.f;
        #pragma unroll
        for (int j = 0; j < 8; j++) {
            sc[j][0] = __expf(sc[j][0] - mn0); sc[j][1] = __expf(sc[j][1] - mn0);
            sc[j][2] = __expf(sc[j][2] - mn1); sc[j][3] = __expf(sc[j][3] - mn1);
            rs0 += sc[j][0] + sc[j][1];
            rs1 += sc[j][2] + sc[j][3];
        }
        rs0 += __shfl_xor_sync(0xffffffffu, rs0, 1);
        rs0 += __shfl_xor_sync(0xffffffffu, rs0, 2);
        rs1 += __shfl_xor_sync(0xffffffffu, rs1, 1);
        rs1 += __shfl_xor_sync(0xffffffffu, rs1, 2);
        l0r = l0r * a0 + rs0;
        l1r = l1r * a1 + rs1;
        #pragma unroll
        for (int j = 0; j < 8; j++) {
            o[j][0] *= a0; o[j][1] *= a0; o[j][2] *= a1; o[j][3] *= a1;
        }
        #pragma unroll
        for (int kk = 0; kk < 4; kk++) {
            uint32_t pa[4];
            __nv_bfloat162 t0 = __float22bfloat162_rn(make_float2(sc[2 * kk][0], sc[2 * kk][1]));
            __nv_bfloat162 t1 = __float22bfloat162_rn(make_float2(sc[2 * kk][2], sc[2 * kk][3]));
            __nv_bfloat162 t2 = __float22bfloat162_rn(make_float2(sc[2 * kk + 1][0], sc[2 * kk + 1][1]));
            __nv_bfloat162 t3 = __float22bfloat162_rn(make_float2(sc[2 * kk + 1][2], sc[2 * kk + 1][3]));
            pa[0] = *(uint32_t*)&t0; pa[1] = *(uint32_t*)&t1;
            pa[2] = *(uint32_t*)&t2; pa[3] = *(uint32_t*)&t3;
            #pragma unroll
            for (int jj = 0; jj < 4; jj++) {
                uint32_t bo = sb + AVT + ((jj << 4) + brow) * 144 + ((kk << 4) + bk) * 2;
                uint32_t b0, b1, b2, b3;
                ldsm4(bo, b0, b1, b2, b3);
                mma_bf16(o[2 * jj],     pa, b0, b1);
                mma_bf16(o[2 * jj + 1], pa, b2, b3);
            }
        }
        __syncthreads();
    }
    const float inv0 = 1.0f / l0r, inv1 = 1.0f / l1r;
    #pragma unroll
    for (int j = 0; j < 8; j++) {
        int col = hc + (j << 3) + (tg << 1);
        size_t r0 = (tok0 + q0 + wq0 + g) * D + col;
        size_t r1 = (tok0 + q0 + wq0 + g + 8) * D + col;
        uint32_t h0, l0, h1, l1;
        splitf2(o[j][0] * inv0, o[j][1] * inv0, h0, l0);
        splitf2(o[j][2] * inv1, o[j][3] * inv1, h1, l1);
        *(uint32_t*)(Oh + r0) = h0; *(uint32_t*)(Ol + r0) = l0;
        *(uint32_t*)(Oh + r1) = h1; *(uint32_t*)(Ol + r1) = l1;
    }
}

// -------------------- conv along feature dim -> split bf16 out --------------------
__global__ __launch_bounds__(128) void conv_row(
    bf16* __restrict__ outH, bf16* __restrict__ outL,
    const float* __restrict__ in, const float* __restrict__ w)
{
    __shared__ float rb[D];
    const int row = blockIdx.x, t = threadIdx.x;
    float4 v = *(const float4*)(in + (size_t)row * D + t * 4);
    *(float4*)&rb[t * 4] = v;
    __syncthreads();
    const float w0 = w[0], w1 = w[1], w2 = w[2];
    float y[4];
    #pragma unroll
    for (int i = 0; i < 4; i++) {
        int c = t * 4 + i;
        float xm = (c > 0) ? rb[c - 1] : 0.f;
        float xp = (c < D - 1) ? rb[c + 1] : 0.f;
        y[i] = w0 * xm + w1 * rb[c] + w2 * xp;
    }
    uint32_t h0, l0, h1, l1;
    splitf2(y[0], y[1], h0, l0);
    splitf2(y[2], y[3], h1, l1);
    *(uint2*)(outH + (size_t)row * D + t * 4) = make_uint2(h0, h1);
    *(uint2*)(outL + (size_t)row * D + t * 4) = make_uint2(l0, l1);
}

// -------------------- LN(a+b)*g+be --------------------
__global__ __launch_bounds__(128) void ln_kernel(
    float* __restrict__ out, bf16* __restrict__ outH, bf16* __restrict__ outL,
    const float* __restrict__ a, const float* __restrict__ b,
    const float* __restrict__ g, const float* __restrict__ be,
    float* __restrict__ hn_out, int do_hn)
{
    __shared__ float sh[8];
    const int row = blockIdx.x, t = threadIdx.x;
    float4 av = *(const float4*)(a + (size_t)row * D + t * 4);
    float4 bv = *(const float4*)(b + (size_t)row * D + t * 4);
    float v[4] = {av.x + bv.x, av.y + bv.y, av.z + bv.z, av.w + bv.w};
    float s = v[0] + v[1] + v[2] + v[3];
    float s2 = v[0] * v[0] + v[1] * v[1] + v[2] * v[2] + v[3] * v[3];
    #pragma unroll
    for (int off = 16; off; off >>= 1) {
        s += __shfl_xor_sync(0xffffffffu, s, off);
        s2 += __shfl_xor_sync(0xffffffffu, s2, off);
    }
    if ((t & 31) == 0) { sh[t >> 5] = s; sh[4 + (t >> 5)] = s2; }
    __syncthreads();
    s = sh[0] + sh[1] + sh[2] + sh[3];
    s2 = sh[4] + sh[5] + sh[6] + sh[7];
    const float mean = s * (1.0f / D);
    const float rstd = rsqrtf(s2 * (1.0f / D) - mean * mean + 1e-5f);
    float4 gv = *(const float4*)(g + t * 4);
    float4 bev = *(const float4*)(be + t * 4);
    float y[4];
    y[0] = (v[0] - mean) * rstd * gv.x + bev.x;
    y[1] = (v[1] - mean) * rstd * gv.y + bev.y;
    y[2] = (v[2] - mean) * rstd * gv.z + bev.z;
    y[3] = (v[3] - mean) * rstd * gv.w + bev.w;
    *(float4*)(out + (size_t)row * D + t * 4) = make_float4(y[0], y[1], y[2], y[3]);
    if (outH) {
        uint32_t h0, l0, h1, l1;
        splitf2(y[0], y[1], h0, l0);
        splitf2(y[2], y[3], h1, l1);
        *(uint2*)(outH + (size_t)row * D + t * 4) = make_uint2(h0, h1);
        *(uint2*)(outL + (size_t)row * D + t * 4) = make_uint2(l0, l1);
    }
    if (do_hn && (row & (SEQL - 1)) == SEQL - 1)
        *(float4*)(hn_out + (size_t)(row >> 10) * D + t * 4) = av;
}

// -------------------- fused LN1 + conv2 --------------------
__global__ __launch_bounds__(128) void ln_conv_kernel(
    float* __restrict__ x1, bf16* __restrict__ x2cH, bf16* __restrict__ x2cL,
    const float* __restrict__ a, const float* __restrict__ b,
    const float* __restrict__ g, const float* __restrict__ be,
    const float* __restrict__ w)
{
    __shared__ float sh[8];
    __shared__ float rb[D];
    const int row = blockIdx.x, t = threadIdx.x;
    float4 av = *(const float4*)(a + (size_t)row * D + t * 4);
    float4 bv = *(const float4*)(b + (size_t)row * D + t * 4);
    float v[4] = {av.x + bv.x, av.y + bv.y, av.z + bv.z, av.w + bv.w};
    float s = v[0] + v[1] + v[2] + v[3];
    float s2 = v[0] * v[0] + v[1] * v[1] + v[2] * v[2] + v[3] * v[3];
    #pragma unroll
    for (int off = 16; off; off >>= 1) {
        s += __shfl_xor_sync(0xffffffffu, s, off);
        s2 += __shfl_xor_sync(0xffffffffu, s2, off);
    }
    if ((t & 31) == 0) { sh[t >> 5] = s; sh[4 + (t >> 5)] = s2; }
    __syncthreads();
    s = sh[0] + sh[1] + sh[2] + sh[3];
    s2 = sh[4] + sh[5] + sh[6] + sh[7];
    const float mean = s * (1.0f / D);
    const float rstd = rsqrtf(s2 * (1.0f / D) - mean * mean + 1e-5f);
    float4 gv = *(const float4*)(g + t * 4);
    float4 bev = *(const float4*)(be + t * 4);
    float y[4];
    y[0] = (v[0] - mean) * rstd * gv.x + bev.x;
    y[1] = (v[1] - mean) * rstd * gv.y + bev.y;
    y[2] = (v[2] - mean) * rstd * gv.z + bev.z;
    y[3] = (v[3] - mean) * rstd * gv.w + bev.w;
    *(float4*)&rb[t * 4] = make_float4(y[0], y[1], y[2], y[3]);
    *(float4*)(x1 + (size_t)row * D + t * 4) = make_float4(y[0], y[1], y[2], y[3]);
    __syncthreads();
    const float w0 = w[0], w1 = w[1], w2 = w[2];
    float z[4];
    #pragma unroll
    for (int i = 0; i < 4; i++) {
        int c = t * 4 + i;
        float xm = (c > 0) ? rb[c - 1] : 0.f;
        float xp = (c < D - 1) ? rb[c + 1] : 0.f;
        z[i] = w0 * xm + w1 * rb[c] + w2 * xp;
    }
    uint32_t h0, l0, h1, l1;
    splitf2(z[0], z[1], h0, l0);
    splitf2(z[2], z[3], h1, l1);
    *(uint2*)(x2cH + (size_t)row * D + t * 4) = make_uint2(h0, h1);
    *(uint2*)(x2cL + (size_t)row * D + t * 4) = make_uint2(l0, l1);
}

// -------------------- launch --------------------
extern "C" void kernel_launch(void* const* d_in, const int* in_sizes, int n_in,
                              void* d_out, int out_size)
{
    const float* input   = (const float*)d_in[0];
    const float* wq_c    = (const float*)d_in[3];
    const float* fc_c    = (const float*)d_in[5];
    const float* wq_g    = (const float*)d_in[6];
    const float* wk_g    = (const float*)d_in[7];
    const float* fc_g    = (const float*)d_in[8];
    const float* wq_x    = (const float*)d_in[9];
    const float* fc_x    = (const float*)d_in[11];
    const float* conv1_w = (const float*)d_in[12];
    const float* conv2_w = (const float*)d_in[13];
    const float* ln1_g = (const float*)d_in[14];
    const float* ln1_b = (const float*)d_in[15];
    const float* ln2_g = (const float*)d_in[16];
    const float* ln2_b = (const float*)d_in[17];
    const float* ln3_g = (const float*)d_in[18];
    const float* ln3_b = (const float*)d_in[19];
    const float* ln4_g = (const float*)d_in[20];
    const float* ln4_b = (const float*)d_in[21];
    const float* mlp_w1 = (const float*)d_in[22];
    const float* mlp_b1 = (const float*)d_in[23];
    const float* mlp_w2 = (const float*)d_in[24];
    const float* mlp_b2 = (const float*)d_in[25];

    float *M1, *M3, *B0, *B1, *B2, *B3, *B4;
    bf16 *Wh, *Wl, *XH, *XL, *C1H, *C1L, *QH, *QL, *KH, *KL, *VB;
    bf16 *ATH, *ATL, *X2CH, *X2CL, *X2H, *X2L, *X3H, *X3L, *HIDH, *HIDL;
    cudaGetSymbolAddress((void**)&M1, d_M1);
    cudaGetSymbolAddress((void**)&M3, d_M3);
    cudaGetSymbolAddress((void**)&B0, d_B0);
    cudaGetSymbolAddress((void**)&B1, d_B1);
    cudaGetSymbolAddress((void**)&B2, d_B2);
    cudaGetSymbolAddress((void**)&B3, d_B3);
    cudaGetSymbolAddress((void**)&B4, d_B4);
    cudaGetSymbolAddress((void**)&Wh, d_Wh);
    cudaGetSymbolAddress((void**)&Wl, d_Wl);
    cudaGetSymbolAddress((void**)&XH, d_XH);
    cudaGetSymbolAddress((void**)&XL, d_XL);
    cudaGetSymbolAddress((void**)&C1H, d_C1H);
    cudaGetSymbolAddress((void**)&C1L, d_C1L);
    cudaGetSymbolAddress((void**)&QH, d_QH);
    cudaGetSymbolAddress((void**)&QL, d_QL);
    cudaGetSymbolAddress((void**)&KH, d_KH);
    cudaGetSymbolAddress((void**)&KL, d_KL);
    cudaGetSymbolAddress((void**)&VB, d_VB);
    cudaGetSymbolAddress((void**)&ATH, d_ATH);
    cudaGetSymbolAddress((void**)&ATL, d_ATL);
    cudaGetSymbolAddress((void**)&X2CH, d_X2CH);
    cudaGetSymbolAddress((void**)&X2CL, d_X2CL);
    cudaGetSymbolAddress((void**)&X2H, d_X2H);
    cudaGetSymbolAddress((void**)&X2L, d_X2L);
    cudaGetSymbolAddress((void**)&X3H, d_X3H);
    cudaGetSymbolAddress((void**)&X3L, d_X3L);
    cudaGetSymbolAddress((void**)&HIDH, d_HIDH);
    cudaGetSymbolAddress((void**)&HIDL, d_HIDL);

    cudaFuncSetAttribute(mma_gemm, cudaFuncAttributeMaxDynamicSharedMemorySize, TCG_SMEM);
    cudaFuncSetAttribute(attn_mma, cudaFuncAttributeMaxDynamicSharedMemorySize, AT_SMEM);

    float* outp = (float*)d_out;
    const size_t out_main = (size_t)N_TOK * D;
    float* hnp = outp + out_main;
    int do_hn = (out_size >= (int)(out_main + BSZ * D)) ? 1 : 0;
    if (!do_hn) hnp = outp;

    const dim3 blk(256);
    const dim3 tg512(D / 128, N_TOK / 128);
    const dim3 tg2048(DFF / 128, N_TOK / 128);
    const dim3 gW(D / 64, D / 64);
    const int nW512 = D * D / 1024;
    const int nW2048 = D * DFF / 1024;
    const int nX = N_TOK * D / 1024;

    gemm_nn<<<gW, blk>>>(M1, fc_c, wq_c, D, D, D);
    gemm_nn<<<gW, blk>>>(M3, fc_x, wq_x, D, D, D);
    split_w<<<nW512, blk>>>(Wh + OFF_WKG, Wl + OFF_WKG, wk_g, D * D);
    split_w<<<nW512, blk>>>(Wh + OFF_WQG, Wl + OFF_WQG, wq_g, D * D);
    split_w<<<nW512, blk>>>(Wh + OFF_M1,  Wl + OFF_M1,  M1, D * D);
    split_w<<<nW512, blk>>>(Wh + OFF_FCG, Wl + OFF_FCG, fc_g, D * D);
    split_w<<<nW512, blk>>>(Wh + OFF_M3,  Wl + OFF_M3,  M3, D * D);
    split_w<<<nW2048, blk>>>(Wh + OFF_W1, Wl + OFF_W1, mlp_w1, D * DFF);
    split_w<<<nW2048, blk>>>(Wh + OFF_W2, Wl + OFF_W2, mlp_w2, D * DFF);
    split_w<<<nX, blk>>>(XH, XL, input, N_TOK * D);

    mma_gemm<<<tg512, blk, TCG_SMEM>>>(nullptr, KH, KL, XH, XL, Wh + OFF_WKG, Wl + OFF_WKG, N_TOK, D, D, nullptr, 0);
    mma_gemm<<<tg512, blk, TCG_SMEM>>>(nullptr, VB, nullptr, XH, XL, Wh + OFF_WQG, Wl + OFF_WQG, N_TOK, D, D, nullptr, 0);

    conv_row<<<N_TOK, 128>>>(C1H, C1L, input, conv1_w);
    mma_gemm<<<tg512, blk, TCG_SMEM>>>(B1, nullptr, nullptr, C1H, C1L, Wh + OFF_M1, Wl + OFF_M1, N_TOK, D, D, nullptr, 0);
    ln_conv_kernel<<<N_TOK, 128>>>(B2, X2CH, X2CL, B1, input, ln1_g, ln1_b, conv2_w);

    mma_gemm<<<tg512, blk, TCG_SMEM>>>(nullptr, QH, QL, X2CH, X2CL, Wh + OFF_WQG, Wl + OFF_WQG, N_TOK, D, D, nullptr, 0);
    attn_mma<<<dim3(SEQL / 128, 8, BSZ), blk, AT_SMEM>>>(ATH, ATL, QH, QL, KH, KL, VB);
    mma_gemm<<<tg512, blk, TCG_SMEM>>>(B0, nullptr, nullptr, ATH, ATL, Wh + OFF_FCG, Wl + OFF_FCG, N_TOK, D, D, nullptr, 0);
    ln_kernel<<<N_TOK, 128>>>(B3, X2H, X2L, B0, B2, ln2_g, ln2_b, hnp, 0);

    mma_gemm<<<tg512, blk, TCG_SMEM>>>(B1, nullptr, nullptr, X2H, X2L, Wh + OFF_M3, Wl + OFF_M3, N_TOK, D, D, nullptr, 0);
    ln_kernel<<<N_TOK, 128>>>(B4, X3H, X3L, B1, B3, ln3_g, ln3_b, hnp, do_hn);

    mma_gemm<<<tg2048, blk, TCG_SMEM>>>(nullptr, HIDH, HIDL, X3H, X3L, Wh + OFF_W1, Wl + OFF_W1, N_TOK, DFF, D, mlp_b1, 1);
    mma_gemm<<<tg512, blk, TCG_SMEM>>>(B0, nullptr, nullptr, HIDH, HIDL, Wh + OFF_W2, Wl + OFF_W2, N_TOK, D, DFF, mlp_b2, 0);
    ln_kernel<<<N_TOK, 128>>>(outp, nullptr, nullptr, B0, B4, ln4_g, ln4_b, hnp, 0);
}